// round 6
// baseline (speedup 1.0000x reference)
#include <cuda_runtime.h>
#include <cstdint>

// Problem constants
#define BATCH 16
#define HDIM  1024
#define WDIM  1024
#define HW    (HDIM * WDIM)
#define NPIX  ((long long)BATCH * HW)

// Tile config
#define TX 128
#define TY 64
#define HALO 5
#define PITCH 144                    // (TX + 2*HALO)=138 padded to mult of 16
#define TROWS (TY + 2*HALO)          // 74
#define NBLOCKS ((WDIM / TX) * (HDIM / TY) * BATCH)   // 2048

// Global accumulators: A0, B0, A1, B1, E  (zero at load; last block re-zeroes each run)
__device__ double g_acc[5];
__device__ unsigned g_bcount;

__device__ __forceinline__ unsigned dp4a_u(unsigned a, unsigned b, unsigned c) {
    return __dp4a(a, b, c);
}

#define ONES 0x01010101u

__global__ __launch_bounds__(256)
void fused_loss_kernel(const float* __restrict__ s0,
                       const float* __restrict__ s1,
                       const int*   __restrict__ tgt,
                       float* __restrict__ out) {
    __shared__ __align__(16) unsigned char s_t[TROWS * PITCH];  // target tile + halo (u8)
    __shared__ __align__(4)  unsigned char s_h[TROWS * TX];     // horizontal 11-sums (u8)
    __shared__ float wred[8][5];
    __shared__ bool is_last;

    const int tid = threadIdx.x;
    const int bx = blockIdx.x, by = blockIdx.y, b = blockIdx.z;
    const int gx0 = bx * TX - HALO;
    const int gy0 = by * TY - HALO;

    // ---- Thread's score geometry (known immediately) ----
    const int xg = tid & 31;           // 32 thread-columns of 4 px
    const int yg = tid >> 5;           // 8 row-groups of 8 rows
    const int x4 = xg * 4;
    const int y0 = yg * 8;
    const int gx = bx * TX + x4;
    const size_t rowBase = (size_t)(by * TY + y0) * WDIM + gx;
    const float* p00 = s0 + (size_t)(2 * b) * HW + rowBase;
    const float* p01 = p00 + HW;
    const float* p10 = s1 + (size_t)(2 * b) * HW + rowBase;
    const float* p11 = p10 + HW;

    // ---- Hoisted j=0 score loads: overlap with target tile load + box filter ----
    float4 va0 = *(const float4*)(p00);
    float4 vc0 = *(const float4*)(p01);
    float4 va1 = *(const float4*)(p10);
    float4 vc1 = *(const float4*)(p11);

    // ---- Phase 1: load target tile (with zero-padded halo) into u8 smem ----
    const int* tb = tgt + (size_t)b * HW;
    for (int i = tid; i < TROWS * PITCH; i += 256) {
        const int r = i / PITCH;
        const int c = i - r * PITCH;
        int v = 0;
        const int gy = gy0 + r;
        const int gxx = gx0 + c;
        if (c < TX + 2*HALO && (unsigned)gy < HDIM && (unsigned)gxx < WDIM)
            v = __ldg(tb + gy * WDIM + gxx);
        s_t[i] = (unsigned char)v;
    }
    __syncthreads();

    // ---- Phase 2: horizontal 11-sums, 4 outputs/iter via masked dp4a ----
    for (int i = tid; i < TROWS * 32; i += 256) {
        const int r = i >> 5;
        const int g = i & 31;
        const unsigned char* row = s_t + r * PITCH + g * 4;
        const unsigned w0 = *(const unsigned*)(row);
        const unsigned w1 = *(const unsigned*)(row + 4);
        const unsigned w2 = *(const unsigned*)(row + 8);
        const unsigned w3 = *(const unsigned*)(row + 12);
        const unsigned o0 = dp4a_u(w0, ONES,        dp4a_u(w1, ONES, dp4a_u(w2, 0x00010101u, 0u)));
        const unsigned o1 = dp4a_u(w0, 0x01010100u, dp4a_u(w1, ONES, dp4a_u(w2, ONES, 0u)));
        const unsigned o2 = dp4a_u(w0, 0x01010000u, dp4a_u(w1, ONES, dp4a_u(w2, ONES, dp4a_u(w3, 0x00000001u, 0u))));
        const unsigned o3 = dp4a_u(w0, 0x01000000u, dp4a_u(w1, ONES, dp4a_u(w2, ONES, dp4a_u(w3, 0x00000101u, 0u))));
        *(unsigned*)(s_h + r * TX + g * 4) = o0 | (o1 << 8) | (o2 << 16) | (o3 << 24);
    }
    __syncthreads();

    // ---- Phase 3: packed vertical sliding 11-sum + fused loss, 4 px/thread ----
    unsigned box = 0;
    #pragma unroll
    for (int r = 0; r < 11; r++)
        box = __vadd4(box, *(const unsigned*)(s_h + (y0 + r) * TX + x4));

    float A0 = 0.f, B0 = 0.f, A1 = 0.f, B1 = 0.f;
    int E = 0;

    #pragma unroll
    for (int j = 0; j < 8; j++) {
        const int y = y0 + j;

        // Prefetch next iteration's score rows (keeps ~8 LDG.128 in flight)
        float4 na0, nc0, na1, nc1;
        if (j < 7) {
            const size_t noff = (size_t)(j + 1) * WDIM;
            na0 = *(const float4*)(p00 + noff);
            nc0 = *(const float4*)(p01 + noff);
            na1 = *(const float4*)(p10 + noff);
            nc1 = *(const float4*)(p11 + noff);
        }

        if (j) {
            box = __vadd4(box, *(const unsigned*)(s_h + (y + 10) * TX + x4));
            box = __vsub4(box, *(const unsigned*)(s_h + (y - 1) * TX + x4));
        }
        // 4 packed center targets (offset 1 mod 4 -> funnel shift of two aligned words)
        const int off = (y + HALO) * PITCH + x4 + 5;
        const unsigned lo = *(const unsigned*)(s_t + off - 1);
        const unsigned hi = *(const unsigned*)(s_t + off + 3);
        const unsigned t4 = __funnelshift_r(lo, hi, 8);      // bytes: t in {0,1}
        const unsigned eq = __vcmpeq4(box, t4 * 121u);       // 0xFF per non-edge byte

        const float a0x[4] = {va0.x, va0.y, va0.z, va0.w};
        const float c0x[4] = {vc0.x, vc0.y, vc0.z, vc0.w};
        const float a1x[4] = {va1.x, va1.y, va1.z, va1.w};
        const float c1x[4] = {vc1.x, vc1.y, vc1.z, vc1.w};

        #pragma unroll
        for (int k = 0; k < 4; k++) {
            const bool t    = (t4 >> (8 * k)) & 1u;
            const bool edge = !((eq >> (8 * k)) & 1u);

            const float a0 = a0x[k], c0 = c0x[k];
            const float a1 = a1x[k], c1 = c1x[k];

            const float lse0 = fmaxf(a0, c0) + __logf(1.0f + __expf(-fabsf(a0 - c0)));
            const float lpa0 = a0 - lse0, lpb0 = c0 - lse0;
            const float lpt0 = t ? lpb0 : lpa0;

            const float lse1 = fmaxf(a1, c1) + __logf(1.0f + __expf(-fabsf(a1 - c1)));
            const float lpa1 = a1 - lse1, lpb1 = c1 - lse1;
            const float lpt1 = t ? lpb1 : lpa1;

            A0 += lpt0;
            A1 += lpt1;
            if (edge) {
                B0 += (lpa0 + lpb0) - 1.5f * lpt0;
                B1 += (lpa1 + lpb1) - 1.5f * lpt1;
                E++;
            }
        }

        va0 = na0; vc0 = nc0; va1 = na1; vc1 = nc1;
    }

    // ---- Block reduction -> 5 double atomics ----
    float vals[5] = {A0, B0, A1, B1, (float)E};
    #pragma unroll
    for (int k = 0; k < 5; k++) {
        #pragma unroll
        for (int off = 16; off; off >>= 1)
            vals[k] += __shfl_down_sync(0xFFFFFFFFu, vals[k], off);
    }
    const int warp = tid >> 5, lane = tid & 31;
    if (lane == 0) {
        #pragma unroll
        for (int k = 0; k < 5; k++) wred[warp][k] = vals[k];
    }
    __syncthreads();
    if (tid == 0) {
        double acc[5] = {0, 0, 0, 0, 0};
        #pragma unroll
        for (int w = 0; w < 8; w++)
            #pragma unroll
            for (int k = 0; k < 5; k++) acc[k] += (double)wred[w][k];
        #pragma unroll
        for (int k = 0; k < 5; k++) atomicAdd(&g_acc[k], acc[k]);
        __threadfence();
        const unsigned done = atomicAdd(&g_bcount, 1u);
        is_last = (done == NBLOCKS - 1);
    }
    __syncthreads();

    // ---- Last block finalizes and resets state for the next graph replay ----
    if (is_last && tid == 0) {
        __threadfence();
        const double N = (double)NPIX;
        double alpha = g_acc[4] / N;
        if (alpha > 0.2) alpha = 0.2;
        const double l0 = -(g_acc[0] + alpha * g_acc[1]) / N;
        const double l1 = -(g_acc[2] + alpha * g_acc[3]) / N;
        out[0] = (float)(l0 + 0.5 * l1);
        #pragma unroll
        for (int k = 0; k < 5; k++) g_acc[k] = 0.0;
        g_bcount = 0u;
    }
}

extern "C" void kernel_launch(void* const* d_in, const int* in_sizes, int n_in,
                              void* d_out, int out_size) {
    const float* s0 = (const float*)d_in[0];
    const float* s1 = (const float*)d_in[1];
    const int*   tg = (const int*)d_in[2];

    dim3 grid(WDIM / TX, HDIM / TY, BATCH);   // (8, 16, 16) = 2048 blocks
    fused_loss_kernel<<<grid, 256>>>(s0, s1, tg, (float*)d_out);
}

// round 13
// speedup vs baseline: 1.1008x; 1.1008x over previous
#include <cuda_runtime.h>
#include <cstdint>

// Problem constants
#define BATCH 16
#define HDIM  1024
#define WDIM  1024
#define HW    (HDIM * WDIM)                  // 1<<20
#define NPIX  ((long long)BATCH * HW)
#define NQUAD ((int)(NPIX / 4))              // 4,194,304 mask bytes

// Tile config (kernel A)
#define TX 128
#define TY 64
#define HALO 5
#define PITCH 144                            // (TX+2*HALO)=138 padded
#define TROWS (TY + 2*HALO)                  // 74

// Kernel B grid
#define B_BLOCKS 1184                        // 148 SMs * 8
#define B_THREADS 256

// Scratch + accumulators (zero-init at load; finalize kernel resets each run)
__device__ unsigned char g_mask[NQUAD];      // per quad: t nibble | edge nibble << 4
__device__ double g_acc[4];                  // A0, B0, A1, B1
__device__ unsigned long long g_E;           // edge count

__device__ __forceinline__ unsigned dp4a_u(unsigned a, unsigned b, unsigned c) {
    return __dp4a(a, b, c);
}

#define ONES 0x01010101u
#define GATH 0x08040201u

// ============================ Kernel A: edge mask ============================
__global__ __launch_bounds__(256)
void edge_mask_kernel(const int* __restrict__ tgt) {
    __shared__ __align__(16) unsigned char s_t[TROWS * PITCH];
    __shared__ __align__(4)  unsigned char s_h[TROWS * TX];
    __shared__ int ered[8];

    const int tid = threadIdx.x;
    const int bx = blockIdx.x, by = blockIdx.y, b = blockIdx.z;
    const int gx0 = bx * TX - HALO;
    const int gy0 = by * TY - HALO;

    // Phase 1: target tile (+halo) -> u8 smem
    const int* tb = tgt + (size_t)b * HW;
    for (int i = tid; i < TROWS * PITCH; i += 256) {
        const int r = i / PITCH;
        const int c = i - r * PITCH;
        int v = 0;
        const int gy = gy0 + r, gx = gx0 + c;
        if (c < TX + 2*HALO && (unsigned)gy < HDIM && (unsigned)gx < WDIM)
            v = __ldg(tb + gy * WDIM + gx);
        s_t[i] = (unsigned char)v;
    }
    __syncthreads();

    // Phase 2: horizontal 11-sums, 4 outputs per iter via masked dp4a
    for (int i = tid; i < TROWS * 32; i += 256) {
        const int r = i >> 5;
        const int g = i & 31;
        const unsigned char* row = s_t + r * PITCH + g * 4;
        const unsigned w0 = *(const unsigned*)(row);
        const unsigned w1 = *(const unsigned*)(row + 4);
        const unsigned w2 = *(const unsigned*)(row + 8);
        const unsigned w3 = *(const unsigned*)(row + 12);
        const unsigned o0 = dp4a_u(w0, ONES,        dp4a_u(w1, ONES, dp4a_u(w2, 0x00010101u, 0u)));
        const unsigned o1 = dp4a_u(w0, 0x01010100u, dp4a_u(w1, ONES, dp4a_u(w2, ONES, 0u)));
        const unsigned o2 = dp4a_u(w0, 0x01010000u, dp4a_u(w1, ONES, dp4a_u(w2, ONES, dp4a_u(w3, 0x00000001u, 0u))));
        const unsigned o3 = dp4a_u(w0, 0x01000000u, dp4a_u(w1, ONES, dp4a_u(w2, ONES, dp4a_u(w3, 0x00000101u, 0u))));
        *(unsigned*)(s_h + r * TX + g * 4) = o0 | (o1 << 8) | (o2 << 16) | (o3 << 24);
    }
    __syncthreads();

    // Phase 3: vertical sliding 11-sum; emit packed mask byte per quad; count E
    const int xg = tid & 31;
    const int yg = tid >> 5;
    const int x4 = xg * 4;
    const int y0 = yg * 8;

    unsigned box = 0;
    #pragma unroll
    for (int r = 0; r < 11; r++)
        box = __vadd4(box, *(const unsigned*)(s_h + (y0 + r) * TX + x4));

    const int qx = bx * 32 + xg;                         // quad column
    unsigned char* mrow = g_mask + (size_t)b * (HW/4);
    int E = 0;

    #pragma unroll
    for (int j = 0; j < 8; j++) {
        const int y = y0 + j;
        if (j) {
            box = __vadd4(box, *(const unsigned*)(s_h + (y + 10) * TX + x4));
            box = __vsub4(box, *(const unsigned*)(s_h + (y - 1) * TX + x4));
        }
        const int off = (y + HALO) * PITCH + x4 + 5;
        const unsigned lo = *(const unsigned*)(s_t + off - 1);
        const unsigned hi = *(const unsigned*)(s_t + off + 3);
        const unsigned t4 = __funnelshift_r(lo, hi, 8);  // 4 target bytes (0/1)
        const unsigned eq = __vcmpeq4(box, t4 * 121u);   // 0xFF where NOT edge
        const unsigned e4 = (~eq) & ONES;                // 1 per edge byte
        E += __popc(e4);
        const unsigned t_nib = dp4a_u(t4, GATH, 0u);     // bits 0..3
        const unsigned e_nib = dp4a_u(e4, GATH, 0u);     // bits 0..3
        mrow[(size_t)(by * TY + y) * (WDIM/4) + qx] =
            (unsigned char)(t_nib | (e_nib << 4));
    }

    // Block-reduce E -> one atomic
    #pragma unroll
    for (int o = 16; o; o >>= 1) E += __shfl_down_sync(0xFFFFFFFFu, E, o);
    const int warp = tid >> 5, lane = tid & 31;
    if (lane == 0) ered[warp] = E;
    __syncthreads();
    if (tid == 0) {
        int s = 0;
        #pragma unroll
        for (int w = 0; w < 8; w++) s += ered[w];
        atomicAdd(&g_E, (unsigned long long)s);
    }
}

// ======================= Kernel B: streaming reduction =======================
__global__ __launch_bounds__(B_THREADS)
void loss_kernel(const float* __restrict__ s0,
                 const float* __restrict__ s1) {
    __shared__ float wred[B_THREADS/32][4];

    const int tid = threadIdx.x;
    const int gtid = blockIdx.x * B_THREADS + tid;

    float A0 = 0.f, B0 = 0.f, A1 = 0.f, B1 = 0.f;

    for (int i = gtid; i < NQUAD; i += B_BLOCKS * B_THREADS) {
        const int b = i >> 18;                    // HW/4 = 2^18 quads per image
        const int q = i & ((HW/4) - 1);
        const size_t base = ((size_t)(2 * b) << 20) + ((size_t)q << 2);

        const float4 va0 = *(const float4*)(s0 + base);
        const float4 vc0 = *(const float4*)(s0 + base + HW);
        const float4 va1 = *(const float4*)(s1 + base);
        const float4 vc1 = *(const float4*)(s1 + base + HW);
        const unsigned m = g_mask[i];

        const float a0x[4] = {va0.x, va0.y, va0.z, va0.w};
        const float c0x[4] = {vc0.x, vc0.y, vc0.z, vc0.w};
        const float a1x[4] = {va1.x, va1.y, va1.z, va1.w};
        const float c1x[4] = {vc1.x, vc1.y, vc1.z, vc1.w};

        #pragma unroll
        for (int k = 0; k < 4; k++) {
            const bool  t  = (m >> k) & 1u;
            const float ef = (float)((m >> (4 + k)) & 1u);

            const float a0 = a0x[k], c0 = c0x[k];
            const float a1 = a1x[k], c1 = c1x[k];

            const float lse0 = fmaxf(a0, c0) + __logf(1.0f + __expf(-fabsf(a0 - c0)));
            const float lpa0 = a0 - lse0, lpb0 = c0 - lse0;
            const float lpt0 = t ? lpb0 : lpa0;

            const float lse1 = fmaxf(a1, c1) + __logf(1.0f + __expf(-fabsf(a1 - c1)));
            const float lpa1 = a1 - lse1, lpb1 = c1 - lse1;
            const float lpt1 = t ? lpb1 : lpa1;

            A0 += lpt0;
            A1 += lpt1;
            B0 += ef * ((lpa0 + lpb0) - 1.5f * lpt0);
            B1 += ef * ((lpa1 + lpb1) - 1.5f * lpt1);
        }
    }

    // Block reduction -> 4 double atomics
    float vals[4] = {A0, B0, A1, B1};
    #pragma unroll
    for (int k = 0; k < 4; k++) {
        #pragma unroll
        for (int o = 16; o; o >>= 1)
            vals[k] += __shfl_down_sync(0xFFFFFFFFu, vals[k], o);
    }
    const int warp = tid >> 5, lane = tid & 31;
    if (lane == 0) {
        #pragma unroll
        for (int k = 0; k < 4; k++) wred[warp][k] = vals[k];
    }
    __syncthreads();
    if (tid == 0) {
        double acc[4] = {0, 0, 0, 0};
        #pragma unroll
        for (int w = 0; w < B_THREADS/32; w++)
            #pragma unroll
            for (int k = 0; k < 4; k++) acc[k] += (double)wred[w][k];
        #pragma unroll
        for (int k = 0; k < 4; k++) atomicAdd(&g_acc[k], acc[k]);
    }
}

// ===================== Kernel C: finalize + state reset ======================
__global__ void finalize_kernel(float* __restrict__ out) {
    const double N = (double)NPIX;
    double alpha = (double)g_E / N;
    if (alpha > 0.2) alpha = 0.2;
    const double l0 = -(g_acc[0] + alpha * g_acc[1]) / N;
    const double l1 = -(g_acc[2] + alpha * g_acc[3]) / N;
    out[0] = (float)(l0 + 0.5 * l1);
    #pragma unroll
    for (int k = 0; k < 4; k++) g_acc[k] = 0.0;
    g_E = 0ull;
}

extern "C" void kernel_launch(void* const* d_in, const int* in_sizes, int n_in,
                              void* d_out, int out_size) {
    const float* s0 = (const float*)d_in[0];
    const float* s1 = (const float*)d_in[1];
    const int*   tg = (const int*)d_in[2];

    dim3 gridA(WDIM / TX, HDIM / TY, BATCH);   // (8, 16, 16) = 2048 blocks
    edge_mask_kernel<<<gridA, 256>>>(tg);
    loss_kernel<<<B_BLOCKS, B_THREADS>>>(s0, s1);
    finalize_kernel<<<1, 1>>>((float*)d_out);
}